// round 15
// baseline (speedup 1.0000x reference)
#include <cuda_runtime.h>
#include <cstdint>
#include <cstddef>

typedef unsigned long long ull;

#define SLICES 96
#define NN 250
#define NP 256
#define SROW 256
#define SEG 18000000ULL   // 96*250*750 elements per output segment
#define OUTQ 4500000u     // float4 quads per segment

// Scratch (device globals; zero-initialized at module load, padding stays 0)
__device__ __align__(16) float g_V[(size_t)SLICES * 256 * 64];
__device__ __align__(16) float g_S[(size_t)SLICES * SROW * NP];
__device__ __align__(16) float g_a[SLICES * NP];
__device__ __align__(16) float g_c[SLICES * NP];
__device__ __align__(16) float g_gv[SLICES * NP];

__constant__ int c_ti3[3] = {0, 0, 1};
__constant__ int c_tj3[3] = {0, 1, 1};

// ---------- f32x2 helpers ----------
__device__ __forceinline__ ull pack2(float x) {
    ull r; asm("mov.b64 %0, {%1, %1};" : "=l"(r) : "f"(x)); return r;
}
__device__ __forceinline__ void fma2(ull& d, ull a, ull b) {
    asm("fma.rn.f32x2 %0, %1, %2, %0;" : "+l"(d) : "l"(a), "l"(b));
}
__device__ __forceinline__ float2 unpack2(ull v) {
    float2 f; asm("mov.b64 {%0, %1}, %2;" : "=f"(f.x), "=f"(f.y) : "l"(v)); return f;
}

// B column permutation -> lane-contiguous pair blocks
__device__ __forceinline__ int bperm(int j) {
    return (((j >> 3) << 2) | (j & 3)) + ((j & 4) << 4);
}

// natural-A + permuted-B inner step: 8 rows x 4 col-pairs
#define MMA_STEP_N(Ak, Bk, ty, tx, acc)                                       \
    do {                                                                      \
        float4 aLo = *(const float4*)&(Ak)[(ty) * 8];                         \
        float4 aHi = *(const float4*)&(Ak)[(ty) * 8 + 4];                     \
        ulonglong2 B01 = *(const ulonglong2*)&(Bk)[(tx) * 4];                 \
        ulonglong2 B23 = *(const ulonglong2*)&(Bk)[64 + (tx) * 4];            \
        ull ad;                                                               \
        ad = pack2(aLo.x);                                                    \
        fma2(acc[0][0], ad, B01.x); fma2(acc[0][1], ad, B01.y);               \
        fma2(acc[0][2], ad, B23.x); fma2(acc[0][3], ad, B23.y);               \
        ad = pack2(aLo.y);                                                    \
        fma2(acc[1][0], ad, B01.x); fma2(acc[1][1], ad, B01.y);               \
        fma2(acc[1][2], ad, B23.x); fma2(acc[1][3], ad, B23.y);               \
        ad = pack2(aLo.z);                                                    \
        fma2(acc[2][0], ad, B01.x); fma2(acc[2][1], ad, B01.y);               \
        fma2(acc[2][2], ad, B23.x); fma2(acc[2][3], ad, B23.y);               \
        ad = pack2(aLo.w);                                                    \
        fma2(acc[3][0], ad, B01.x); fma2(acc[3][1], ad, B01.y);               \
        fma2(acc[3][2], ad, B23.x); fma2(acc[3][3], ad, B23.y);               \
        ad = pack2(aHi.x);                                                    \
        fma2(acc[4][0], ad, B01.x); fma2(acc[4][1], ad, B01.y);               \
        fma2(acc[4][2], ad, B23.x); fma2(acc[4][3], ad, B23.y);               \
        ad = pack2(aHi.y);                                                    \
        fma2(acc[5][0], ad, B01.x); fma2(acc[5][1], ad, B01.y);               \
        fma2(acc[5][2], ad, B23.x); fma2(acc[5][3], ad, B23.y);               \
        ad = pack2(aHi.z);                                                    \
        fma2(acc[6][0], ad, B01.x); fma2(acc[6][1], ad, B01.y);               \
        fma2(acc[6][2], ad, B23.x); fma2(acc[6][3], ad, B23.y);               \
        ad = pack2(aHi.w);                                                    \
        fma2(acc[7][0], ad, B01.x); fma2(acc[7][1], ad, B01.y);               \
        fma2(acc[7][2], ad, B23.x); fma2(acc[7][3], ad, B23.y);               \
    } while (0)

// ---------- K1: nodevec = tanh(concat(X) @ W + b), f32x2 ----------
__global__ void __launch_bounds__(256) k_embed(
    const float* __restrict__ hist, const float* __restrict__ prior,
    const float* __restrict__ obs, const float* __restrict__ W,
    const float* __restrict__ bias)
{
    __shared__ ull Xd[16][224];
    __shared__ ull Ws[64 * 32];
    int tid = threadIdx.x;
    int row0 = blockIdx.x * 16;

    for (int t = tid; t < 16 * 224; t += 256) {
        int r = t / 224, k = t - r * 224;
        int g = row0 + r;
        float v;
        if (k < 128)      v = hist [g * 128 + k];
        else if (k < 192) v = prior[g * 64  + (k - 128)];
        else              v = obs  [g * 32  + (k - 192)];
        Xd[r][k] = pack2(v);
    }

    int cp = tid & 31, rg = tid >> 5;
    ull acc0 = 0ULL, acc1 = 0ULL;
    const ull* Wg = (const ull*)W;

    for (int k0 = 0; k0 < 224; k0 += 64) {
        int kn = (224 - k0 < 64) ? (224 - k0) : 64;
        __syncthreads();
        for (int t = tid; t < kn * 32; t += 256) Ws[t] = Wg[(size_t)k0 * 32 + t];
        __syncthreads();
#pragma unroll 8
        for (int k = 0; k < kn; k++) {
            ull w = Ws[k * 32 + cp];
            fma2(acc0, Xd[rg][k0 + k], w);
            fma2(acc1, Xd[rg + 8][k0 + k], w);
        }
    }

    float2 b2 = *(const float2*)&bias[cp * 2];
    float2 r0 = unpack2(acc0), r1 = unpack2(acc1);
    float2 o0 = { tanhf(r0.x + b2.x), tanhf(r0.y + b2.y) };
    float2 o1 = { tanhf(r1.x + b2.x), tanhf(r1.y + b2.y) };
    int g0 = row0 + rg;
    int s0 = g0 / 250;
    *(float2*)&g_V[(size_t)(s0 * 256 + g0 - s0 * 250) * 64 + cp * 2] = o0;
    int g1 = row0 + rg + 8;
    int s1 = g1 / 250;
    *(float2*)&g_V[(size_t)(s1 * 256 + g1 - s1 * 250) * 64 + cp * 2] = o1;
}

// ---------- K2: S = relu(V V^T)  (R11 structure: one sync/chunk) ----------
__global__ void __launch_bounds__(256, 2) k_sim()
{
    __shared__ __align__(16) float As[2][16][132];
    __shared__ __align__(16) float Bs[2][16][132];
    int slice = blockIdx.y;
    int ti = c_ti3[blockIdx.x], tj = c_tj3[blockIdx.x];
    int i0 = ti * 128, j0 = tj * 128;
    bool diag = (ti == tj);
    int tid = threadIdx.x;
    int tx = tid & 15, ty = tid >> 4;
    int sk = tid & 15, sr0 = tid >> 4;
    const float* Vb = g_V + (size_t)slice * 256 * 64;

    ull acc[8][4];
#pragma unroll
    for (int r = 0; r < 8; r++)
#pragma unroll
        for (int q = 0; q < 4; q++) acc[r][q] = 0ULL;

    float pa[8], pb[8];
#pragma unroll
    for (int u = 0; u < 8; u++) {
        int r = sr0 + u * 16;
        pa[u] = Vb[(size_t)(i0 + r) * 64 + sk];
        pb[u] = diag ? pa[u] : Vb[(size_t)(j0 + r) * 64 + sk];
    }

    for (int c = 0; c < 4; c++) {
        int buf = c & 1;
#pragma unroll
        for (int u = 0; u < 8; u++) {
            int r = sr0 + u * 16;
            As[buf][sk][r] = pa[u];
            Bs[buf][sk][bperm(r)] = pb[u];
        }
        __syncthreads();
        if (c < 3) {
            int kk = (c + 1) * 16 + sk;
#pragma unroll
            for (int u = 0; u < 8; u++) {
                int r = sr0 + u * 16;
                pa[u] = Vb[(size_t)(i0 + r) * 64 + kk];
                pb[u] = diag ? pa[u] : Vb[(size_t)(j0 + r) * 64 + kk];
            }
        }
#pragma unroll
        for (int k = 0; k < 16; k++) MMA_STEP_N(As[buf][k], Bs[buf][k], ty, tx, acc);
    }

    float v[8][8];
#pragma unroll
    for (int r = 0; r < 8; r++)
#pragma unroll
        for (int q = 0; q < 4; q++) {
            float2 f = unpack2(acc[r][q]);
            v[r][2 * q]     = fmaxf(f.x, 0.f);
            v[r][2 * q + 1] = fmaxf(f.y, 0.f);
        }

    float* Sb = g_S + (size_t)slice * SROW * NP;
    int ib = i0 + ty * 8, jb = j0 + tx * 8;
#pragma unroll
    for (int r = 0; r < 8; r++) {
        *(float4*)&Sb[(size_t)(ib + r) * NP + jb]     = make_float4(v[r][0], v[r][1], v[r][2], v[r][3]);
        *(float4*)&Sb[(size_t)(ib + r) * NP + jb + 4] = make_float4(v[r][4], v[r][5], v[r][6], v[r][7]);
    }
    if (!diag) {
#pragma unroll
        for (int q = 0; q < 8; q++) {
            *(float4*)&Sb[(size_t)(jb + q) * NP + ib]     = make_float4(v[0][q], v[1][q], v[2][q], v[3][q]);
            *(float4*)&Sb[(size_t)(jb + q) * NP + ib + 4] = make_float4(v[4][q], v[5][q], v[6][q], v[7][q]);
        }
    }
}

// ---------- K3: scalars via column reductions (coalesced) ----------
__global__ void __launch_bounds__(256) k_scal()
{
    int slice = blockIdx.x;
    int j = threadIdx.x;
    __shared__ float ds[NP];
    const float* Sb = g_S + (size_t)slice * SROW * NP;

    float s = 0.f;
#pragma unroll 5
    for (int r = 0; r < NN; r++) s += Sb[(size_t)r * NP + j];
    float d = (j < NN) ? rsqrtf(s + 1e-9f) : 0.f;
    ds[j] = d;
    __syncthreads();

    float t = 0.f;
#pragma unroll 5
    for (int r = 0; r < NN; r++) t = fmaf(Sb[(size_t)r * NP + j], ds[r], t);

    float a = 0.f, c = 0.f, gv = 0.f;
    if (j < NN) {
        float r = d * t + 1e-9f;
        a = d; c = d / r; gv = d * c;
    }
    g_a[slice * NP + j] = a;
    g_c[slice * NP + j] = c;
    g_gv[slice * NP + j] = gv;
}

// write one 8-float run into segs 1 and 3 with 3x temporal tiling, float2
// stores (row bases are only 8B-aligned), pair-wise clipped at column NN.
__device__ __forceinline__ void emit_row8(
    float* __restrict__ out, int slice, int row, int col0, const float* w)
{
    size_t rowbase = ((size_t)(slice * NN + row)) * 750;
#pragma unroll
    for (int ss = 0; ss < 2; ss++) {
        float* o = out + (ss ? 3 * SEG : SEG) + rowbase;
#pragma unroll
        for (int kt = 0; kt < 3; kt++) {
            float* p = o + kt * 250 + col0;
#pragma unroll
            for (int pr = 0; pr < 4; pr++) {
                if (col0 + 2 * pr <= NN - 2)
                    *(float2*)(p + 2 * pr) = make_float2(w[2 * pr], w[2 * pr + 1]);
            }
        }
    }
}

// ---------- K4: M = S diag(g) S, fused order-2 output -> seg1, seg3 ----------
__global__ void __launch_bounds__(256, 2) k_gemm2(float* __restrict__ out)
{
    __shared__ __align__(16) float As[2][16][132];
    __shared__ __align__(16) float Bs[2][16][132];
    int slice = blockIdx.y;
    int ti = c_ti3[blockIdx.x], tj = c_tj3[blockIdx.x];
    int i0 = ti * 128, j0 = tj * 128;
    bool diag = (ti == tj);
    int tid = threadIdx.x;
    int tx = tid & 15, ty = tid >> 4;
    int sk = tid & 15, sr0 = tid >> 4;
    const float* Sb = g_S + (size_t)slice * SROW * NP;
    const float* gg = g_gv + slice * NP;

    ull acc[8][4];
#pragma unroll
    for (int r = 0; r < 8; r++)
#pragma unroll
        for (int q = 0; q < 4; q++) acc[r][q] = 0ULL;

    float pa[8], pb[8];
    {
        float gk = gg[sk];
#pragma unroll
        for (int u = 0; u < 8; u++) {
            int r = sr0 + u * 16;
            pa[u] = Sb[(size_t)(i0 + r) * NP + sk];
            pb[u] = gk * Sb[(size_t)(j0 + r) * NP + sk];
        }
    }

    for (int c = 0; c < 16; c++) {
        int buf = c & 1;
#pragma unroll
        for (int u = 0; u < 8; u++) {
            int r = sr0 + u * 16;
            As[buf][sk][r] = pa[u];
            Bs[buf][sk][bperm(r)] = pb[u];
        }
        __syncthreads();
        if (c < 15) {
            int kk = (c + 1) * 16 + sk;
            float gk = gg[kk];
#pragma unroll
            for (int u = 0; u < 8; u++) {
                int r = sr0 + u * 16;
                pa[u] = Sb[(size_t)(i0 + r) * NP + kk];
                pb[u] = gk * Sb[(size_t)(j0 + r) * NP + kk];
            }
        }
#pragma unroll
        for (int k = 0; k < 16; k++) MMA_STEP_N(As[buf][k], Bs[buf][k], ty, tx, acc);
    }

    float m[8][8];
#pragma unroll
    for (int r = 0; r < 8; r++)
#pragma unroll
        for (int q = 0; q < 4; q++) {
            float2 f = unpack2(acc[r][q]);
            m[r][2 * q] = f.x;
            m[r][2 * q + 1] = f.y;
        }

    int soff = slice * NP;
    int ib = i0 + ty * 8, jb = j0 + tx * 8;
    float4 cjA = *(const float4*)&g_c[soff + jb];
    float4 cjB = *(const float4*)&g_c[soff + jb + 4];
    float4 aiA = *(const float4*)&g_a[soff + ib];
    float4 aiB = *(const float4*)&g_a[soff + ib + 4];
    float aiv[8] = {aiA.x, aiA.y, aiA.z, aiA.w, aiB.x, aiB.y, aiB.z, aiB.w};
    float cjv[8] = {cjA.x, cjA.y, cjA.z, cjA.w, cjB.x, cjB.y, cjB.z, cjB.w};

    if (diag && tx == ty) {
#pragma unroll
        for (int r = 0; r < 8; r++) m[r][r] = 0.f;
    }

    // normal orientation: P2'[i][j] = a_i * M[i][j] * c_j  -> out segs 1,3
#pragma unroll
    for (int r = 0; r < 8; r++) {
        int i = ib + r;
        if (i < NN) {
            float ai = aiv[r];
            float w[8];
#pragma unroll
            for (int q = 0; q < 8; q++) w[q] = ai * m[r][q] * cjv[q];
            emit_row8(out, slice, i, jb, w);
        }
    }

    // transposed block (off-diag only, here always (0,1)): P2'[j][i] = a_j * M[i][j] * c_i
    if (!diag) {
        float4 ciA = *(const float4*)&g_c[soff + ib];
        float4 ciB = *(const float4*)&g_c[soff + ib + 4];
        float4 ajA = *(const float4*)&g_a[soff + jb];
        float4 ajB = *(const float4*)&g_a[soff + jb + 4];
        float civ[8] = {ciA.x, ciA.y, ciA.z, ciA.w, ciB.x, ciB.y, ciB.z, ciB.w};
        float ajv[8] = {ajA.x, ajA.y, ajA.z, ajA.w, ajB.x, ajB.y, ajB.z, ajB.w};
#pragma unroll
        for (int q = 0; q < 8; q++) {
            int j = jb + q;
            if (j < NN) {
                float aj = ajv[q];
                float w[8];
#pragma unroll
                for (int r = 0; r < 8; r++) w[r] = aj * m[r][q] * civ[r];
                emit_row8(out, slice, j, ib, w);
            }
        }
    }
}

// ---------- K5: order-1 segments (0, 2), flat float4 ----------
__global__ void __launch_bounds__(256) k_out1(float* __restrict__ out)
{
    unsigned f = blockIdx.x * 256 + threadIdx.x;
    if (f >= OUTQ) return;
    unsigned e0 = f * 4;
    unsigned ng = e0 / 750u;
    unsigned pos = e0 - ng * 750u;
    unsigned sl = ng / 250u;
    unsigned nn = ng - sl * 250u;

    float v1[4];
    unsigned pe = pos;
#pragma unroll
    for (int e = 0; e < 4; e++) {
        if (pe >= 750u) { pe -= 750u; nn += 1; if (nn == 250u) { nn = 0; sl += 1; } }
        unsigned m = pe;
        if (m >= 500u) m -= 500u; else if (m >= 250u) m -= 250u;
        float s = g_S[((size_t)sl * SROW + nn) * NP + m];
        float a = g_a[sl * NP + nn];
        float c = g_c[sl * NP + m];
        v1[e] = (m == nn) ? 0.f : a * s * c;
        pe += 1;
    }
    float4 V1 = make_float4(v1[0], v1[1], v1[2], v1[3]);
    *(float4*)&out[e0]           = V1;
    *(float4*)&out[2 * SEG + e0] = V1;
}

extern "C" void kernel_launch(void* const* d_in, const int* in_sizes, int n_in,
                              void* d_out, int out_size)
{
    const float* hist  = (const float*)d_in[0];
    const float* prior = (const float*)d_in[1];
    const float* obs   = (const float*)d_in[2];
    const float* W     = (const float*)d_in[3];
    const float* bias  = (const float*)d_in[4];
    float* out = (float*)d_out;

    // one-time resource init (handles only; identical launched work every call)
    static cudaStream_t s2 = nullptr;
    static cudaEvent_t evFork = nullptr, evJoin = nullptr;
    if (s2 == nullptr) {
        cudaStreamCreateWithFlags(&s2, cudaStreamNonBlocking);
        cudaEventCreateWithFlags(&evFork, cudaEventDisableTiming);
        cudaEventCreateWithFlags(&evJoin, cudaEventDisableTiming);
    }

    k_embed<<<1500, 256>>>(hist, prior, obs, W, bias);
    k_sim  <<<dim3(3, SLICES), 256>>>();
    k_scal <<<SLICES, 256>>>();

    // fork: out1 (order-1 segments) runs concurrently with fused gemm2
    cudaEventRecord(evFork, 0);
    cudaStreamWaitEvent(s2, evFork, 0);

    k_gemm2<<<dim3(3, SLICES), 256>>>(out);                  // stream 0, profile idx 3
    k_out1 <<<(OUTQ + 255) / 256, 256, 0, s2>>>(out);        // stream s2, concurrent

    cudaEventRecord(evJoin, s2);
    cudaStreamWaitEvent(0, evJoin, 0);
}

// round 16
// speedup vs baseline: 1.4177x; 1.4177x over previous
#include <cuda_runtime.h>
#include <cstdint>
#include <cstddef>

typedef unsigned long long ull;

#define SLICES 96
#define NN 250
#define NP 256
#define SROW 256
#define SEG 18000000ULL   // 96*250*750 elements per output segment
#define OUTQ 4500000u     // float4 quads per segment

// Scratch (device globals; zero-initialized at module load, padding stays 0)
__device__ __align__(16) float g_V[(size_t)SLICES * 256 * 64];
__device__ __align__(16) float g_S[(size_t)SLICES * SROW * NP];
__device__ __align__(16) float g_P2[(size_t)SLICES * SROW * NP];
__device__ __align__(16) float g_rs[2][SLICES * NP];   // rowsum partials (2 deterministic slots)
__device__ __align__(16) float g_tp[4 * SLICES * NP];  // t = S*d partials (4 row-chunks)
__device__ __align__(16) float g_a[SLICES * NP];
__device__ __align__(16) float g_c[SLICES * NP];
__device__ __align__(16) float g_gv[SLICES * NP];

__constant__ int c_ti3[3] = {0, 0, 1};
__constant__ int c_tj3[3] = {0, 1, 1};

// ---------- f32x2 helpers ----------
__device__ __forceinline__ ull pack2(float x) {
    ull r; asm("mov.b64 %0, {%1, %1};" : "=l"(r) : "f"(x)); return r;
}
__device__ __forceinline__ void fma2(ull& d, ull a, ull b) {
    asm("fma.rn.f32x2 %0, %1, %2, %0;" : "+l"(d) : "l"(a), "l"(b));
}
__device__ __forceinline__ float2 unpack2(ull v) {
    float2 f; asm("mov.b64 {%0, %1}, %2;" : "=f"(f.x), "=f"(f.y) : "l"(v)); return f;
}

// B column permutation -> lane-contiguous pair blocks
__device__ __forceinline__ int bperm(int j) {
    return (((j >> 3) << 2) | (j & 3)) + ((j & 4) << 4);
}

// natural-A + permuted-B inner step: 8 rows x 4 col-pairs
#define MMA_STEP_N(Ak, Bk, ty, tx, acc)                                       \
    do {                                                                      \
        float4 aLo = *(const float4*)&(Ak)[(ty) * 8];                         \
        float4 aHi = *(const float4*)&(Ak)[(ty) * 8 + 4];                     \
        ulonglong2 B01 = *(const ulonglong2*)&(Bk)[(tx) * 4];                 \
        ulonglong2 B23 = *(const ulonglong2*)&(Bk)[64 + (tx) * 4];            \
        ull ad;                                                               \
        ad = pack2(aLo.x);                                                    \
        fma2(acc[0][0], ad, B01.x); fma2(acc[0][1], ad, B01.y);               \
        fma2(acc[0][2], ad, B23.x); fma2(acc[0][3], ad, B23.y);               \
        ad = pack2(aLo.y);                                                    \
        fma2(acc[1][0], ad, B01.x); fma2(acc[1][1], ad, B01.y);               \
        fma2(acc[1][2], ad, B23.x); fma2(acc[1][3], ad, B23.y);               \
        ad = pack2(aLo.z);                                                    \
        fma2(acc[2][0], ad, B01.x); fma2(acc[2][1], ad, B01.y);               \
        fma2(acc[2][2], ad, B23.x); fma2(acc[2][3], ad, B23.y);               \
        ad = pack2(aLo.w);                                                    \
        fma2(acc[3][0], ad, B01.x); fma2(acc[3][1], ad, B01.y);               \
        fma2(acc[3][2], ad, B23.x); fma2(acc[3][3], ad, B23.y);               \
        ad = pack2(aHi.x);                                                    \
        fma2(acc[4][0], ad, B01.x); fma2(acc[4][1], ad, B01.y);               \
        fma2(acc[4][2], ad, B23.x); fma2(acc[4][3], ad, B23.y);               \
        ad = pack2(aHi.y);                                                    \
        fma2(acc[5][0], ad, B01.x); fma2(acc[5][1], ad, B01.y);               \
        fma2(acc[5][2], ad, B23.x); fma2(acc[5][3], ad, B23.y);               \
        ad = pack2(aHi.z);                                                    \
        fma2(acc[6][0], ad, B01.x); fma2(acc[6][1], ad, B01.y);               \
        fma2(acc[6][2], ad, B23.x); fma2(acc[6][3], ad, B23.y);               \
        ad = pack2(aHi.w);                                                    \
        fma2(acc[7][0], ad, B01.x); fma2(acc[7][1], ad, B01.y);               \
        fma2(acc[7][2], ad, B23.x); fma2(acc[7][3], ad, B23.y);               \
    } while (0)

// ---------- K1: nodevec = tanh(concat(X) @ W + b), f32x2 ----------
__global__ void __launch_bounds__(256) k_embed(
    const float* __restrict__ hist, const float* __restrict__ prior,
    const float* __restrict__ obs, const float* __restrict__ W,
    const float* __restrict__ bias)
{
    __shared__ ull Xd[16][224];
    __shared__ ull Ws[64 * 32];
    int tid = threadIdx.x;
    int row0 = blockIdx.x * 16;

    for (int t = tid; t < 16 * 224; t += 256) {
        int r = t / 224, k = t - r * 224;
        int g = row0 + r;
        float v;
        if (k < 128)      v = hist [g * 128 + k];
        else if (k < 192) v = prior[g * 64  + (k - 128)];
        else              v = obs  [g * 32  + (k - 192)];
        Xd[r][k] = pack2(v);
    }

    int cp = tid & 31, rg = tid >> 5;
    ull acc0 = 0ULL, acc1 = 0ULL;
    const ull* Wg = (const ull*)W;

    for (int k0 = 0; k0 < 224; k0 += 64) {
        int kn = (224 - k0 < 64) ? (224 - k0) : 64;
        __syncthreads();
        for (int t = tid; t < kn * 32; t += 256) Ws[t] = Wg[(size_t)k0 * 32 + t];
        __syncthreads();
#pragma unroll 8
        for (int k = 0; k < kn; k++) {
            ull w = Ws[k * 32 + cp];
            fma2(acc0, Xd[rg][k0 + k], w);
            fma2(acc1, Xd[rg + 8][k0 + k], w);
        }
    }

    float2 b2 = *(const float2*)&bias[cp * 2];
    float2 r0 = unpack2(acc0), r1 = unpack2(acc1);
    float2 o0 = { tanhf(r0.x + b2.x), tanhf(r0.y + b2.y) };
    float2 o1 = { tanhf(r1.x + b2.x), tanhf(r1.y + b2.y) };
    int g0 = row0 + rg;
    int s0 = g0 / 250;
    *(float2*)&g_V[(size_t)(s0 * 256 + g0 - s0 * 250) * 64 + cp * 2] = o0;
    int g1 = row0 + rg + 8;
    int s1 = g1 / 250;
    *(float2*)&g_V[(size_t)(s1 * 256 + g1 - s1 * 250) * 64 + cp * 2] = o1;
}

// ---------- K2: S = relu(V V^T) + deterministic rowsum partials ----------
__global__ void __launch_bounds__(256, 2) k_sim()
{
    __shared__ __align__(16) float As[2][16][132];
    __shared__ __align__(16) float Bs[2][16][132];
    int slice = blockIdx.y;
    int ti = c_ti3[blockIdx.x], tj = c_tj3[blockIdx.x];
    int i0 = ti * 128, j0 = tj * 128;
    bool diag = (ti == tj);
    int tid = threadIdx.x;
    int tx = tid & 15, ty = tid >> 4;
    int sk = tid & 15, sr0 = tid >> 4;
    const float* Vb = g_V + (size_t)slice * 256 * 64;

    ull acc[8][4];
#pragma unroll
    for (int r = 0; r < 8; r++)
#pragma unroll
        for (int q = 0; q < 4; q++) acc[r][q] = 0ULL;

    float pa[8], pb[8];
#pragma unroll
    for (int u = 0; u < 8; u++) {
        int r = sr0 + u * 16;
        pa[u] = Vb[(size_t)(i0 + r) * 64 + sk];
        pb[u] = diag ? pa[u] : Vb[(size_t)(j0 + r) * 64 + sk];
    }

    for (int c = 0; c < 4; c++) {
        int buf = c & 1;
#pragma unroll
        for (int u = 0; u < 8; u++) {
            int r = sr0 + u * 16;
            As[buf][sk][r] = pa[u];
            Bs[buf][sk][bperm(r)] = pb[u];
        }
        __syncthreads();
        if (c < 3) {
            int kk = (c + 1) * 16 + sk;
#pragma unroll
            for (int u = 0; u < 8; u++) {
                int r = sr0 + u * 16;
                pa[u] = Vb[(size_t)(i0 + r) * 64 + kk];
                pb[u] = diag ? pa[u] : Vb[(size_t)(j0 + r) * 64 + kk];
            }
        }
#pragma unroll
        for (int k = 0; k < 16; k++) MMA_STEP_N(As[buf][k], Bs[buf][k], ty, tx, acc);
    }

    float v[8][8];
#pragma unroll
    for (int r = 0; r < 8; r++)
#pragma unroll
        for (int q = 0; q < 4; q++) {
            float2 f = unpack2(acc[r][q]);
            v[r][2 * q]     = fmaxf(f.x, 0.f);
            v[r][2 * q + 1] = fmaxf(f.y, 0.f);
        }

    float* Sb = g_S + (size_t)slice * SROW * NP;
    int ib = i0 + ty * 8, jb = j0 + tx * 8;
#pragma unroll
    for (int r = 0; r < 8; r++) {
        *(float4*)&Sb[(size_t)(ib + r) * NP + jb]     = make_float4(v[r][0], v[r][1], v[r][2], v[r][3]);
        *(float4*)&Sb[(size_t)(ib + r) * NP + jb + 4] = make_float4(v[r][4], v[r][5], v[r][6], v[r][7]);
    }
    if (!diag) {
#pragma unroll
        for (int q = 0; q < 8; q++) {
            *(float4*)&Sb[(size_t)(jb + q) * NP + ib]     = make_float4(v[0][q], v[1][q], v[2][q], v[3][q]);
            *(float4*)&Sb[(size_t)(jb + q) * NP + ib + 4] = make_float4(v[4][q], v[5][q], v[6][q], v[7][q]);
        }
    }

    // ----- rowsum partials -----
    // normal rows (slot tj): reduce this thread's 8 cols, then across the 16 tx lanes
#pragma unroll
    for (int r = 0; r < 8; r++) {
        float rp = ((v[r][0] + v[r][1]) + (v[r][2] + v[r][3]))
                 + ((v[r][4] + v[r][5]) + (v[r][6] + v[r][7]));
        rp += __shfl_xor_sync(0xffffffffu, rp, 8);
        rp += __shfl_xor_sync(0xffffffffu, rp, 4);
        rp += __shfl_xor_sync(0xffffffffu, rp, 2);
        rp += __shfl_xor_sync(0xffffffffu, rp, 1);
        if (tx == 0) g_rs[tj][slice * NP + ib + r] = rp;
    }
    // transposed rows (off-diag only; slot ti): cross-warp reduce via reused smem
    if (!diag) {
        float (*sm)[132] = (float(*)[132])As;   // first 16x132 region of As
#pragma unroll
        for (int q = 0; q < 8; q++) {
            float tq = ((v[0][q] + v[1][q]) + (v[2][q] + v[3][q]))
                     + ((v[4][q] + v[5][q]) + (v[6][q] + v[7][q]));
            sm[ty][tx * 8 + q] = tq;
        }
        __syncthreads();
        if (tid < 128) {
            float s = 0.f;
#pragma unroll
            for (int p = 0; p < 16; p++) s += sm[p][tid];
            g_rs[ti][slice * NP + j0 + tid] = s;
        }
    }
}

// ---------- K3a: partial t = S * d over 64-row chunks (coalesced, 384 CTAs) ----------
__global__ void __launch_bounds__(256) k_scal_t()
{
    int slice = blockIdx.y;
    int p = blockIdx.x;
    int j = threadIdx.x;
    __shared__ float ds[NP];
    float s = g_rs[0][slice * NP + j] + g_rs[1][slice * NP + j];
    ds[j] = rsqrtf(s + 1e-9f);      // padded rows: s=0 -> finite, multiplied by S=0
    __syncthreads();

    const float* Sb = g_S + (size_t)slice * SROW * NP;
    int r0 = p * 64;
    float t = 0.f;
#pragma unroll 8
    for (int rr = 0; rr < 64; rr++) {
        int r = r0 + rr;
        t = fmaf(Sb[(size_t)r * NP + j], ds[r], t);
    }
    g_tp[(slice * 4 + p) * NP + j] = t;
}

// ---------- K3b: finisher -> a = d, c = d/r, g = d^2/r ----------
__global__ void __launch_bounds__(256) k_scal_fin()
{
    int slice = blockIdx.x;
    int j = threadIdx.x;
    float s = g_rs[0][slice * NP + j] + g_rs[1][slice * NP + j];
    float t = g_tp[(slice * 4 + 0) * NP + j] + g_tp[(slice * 4 + 1) * NP + j]
            + g_tp[(slice * 4 + 2) * NP + j] + g_tp[(slice * 4 + 3) * NP + j];
    float a = 0.f, c = 0.f, gv = 0.f;
    if (j < NN) {
        float d = rsqrtf(s + 1e-9f);
        float r = d * t + 1e-9f;
        a = d; c = d / r; gv = d * c;
    }
    g_a[slice * NP + j] = a;
    g_c[slice * NP + j] = c;
    g_gv[slice * NP + j] = gv;
}

// ---------- K4: M = S diag(g) S  (R11/R14 frozen structure) -> g_P2 ----------
__global__ void __launch_bounds__(256, 2) k_gemm2()
{
    __shared__ __align__(16) float As[2][16][132];
    __shared__ __align__(16) float Bs[2][16][132];
    int slice = blockIdx.y;
    int ti = c_ti3[blockIdx.x], tj = c_tj3[blockIdx.x];
    int i0 = ti * 128, j0 = tj * 128;
    bool diag = (ti == tj);
    int tid = threadIdx.x;
    int tx = tid & 15, ty = tid >> 4;
    int sk = tid & 15, sr0 = tid >> 4;
    const float* Sb = g_S + (size_t)slice * SROW * NP;
    const float* gg = g_gv + slice * NP;
    float* P2b = g_P2 + (size_t)slice * SROW * NP;

    ull acc[8][4];
#pragma unroll
    for (int r = 0; r < 8; r++)
#pragma unroll
        for (int q = 0; q < 4; q++) acc[r][q] = 0ULL;

    float pa[8], pb[8];
    {
        float gk = gg[sk];
#pragma unroll
        for (int u = 0; u < 8; u++) {
            int r = sr0 + u * 16;
            pa[u] = Sb[(size_t)(i0 + r) * NP + sk];
            pb[u] = gk * Sb[(size_t)(j0 + r) * NP + sk];
        }
    }

    for (int c = 0; c < 16; c++) {
        int buf = c & 1;
#pragma unroll
        for (int u = 0; u < 8; u++) {
            int r = sr0 + u * 16;
            As[buf][sk][r] = pa[u];
            Bs[buf][sk][bperm(r)] = pb[u];
        }
        __syncthreads();
        if (c < 15) {
            int kk = (c + 1) * 16 + sk;
            float gk = gg[kk];
#pragma unroll
            for (int u = 0; u < 8; u++) {
                int r = sr0 + u * 16;
                pa[u] = Sb[(size_t)(i0 + r) * NP + kk];
                pb[u] = gk * Sb[(size_t)(j0 + r) * NP + kk];
            }
        }
#pragma unroll
        for (int k = 0; k < 16; k++) MMA_STEP_N(As[buf][k], Bs[buf][k], ty, tx, acc);
    }

    float m[8][8];
#pragma unroll
    for (int r = 0; r < 8; r++)
#pragma unroll
        for (int q = 0; q < 4; q++) {
            float2 f = unpack2(acc[r][q]);
            m[r][2 * q] = f.x;
            m[r][2 * q + 1] = f.y;
        }

    int soff = slice * NP;
    int ib = i0 + ty * 8, jb = j0 + tx * 8;
    float4 cjA = *(const float4*)&g_c[soff + jb];
    float4 cjB = *(const float4*)&g_c[soff + jb + 4];
    float4 aiA = *(const float4*)&g_a[soff + ib];
    float4 aiB = *(const float4*)&g_a[soff + ib + 4];
    float aiv[8] = {aiA.x, aiA.y, aiA.z, aiA.w, aiB.x, aiB.y, aiB.z, aiB.w};
    float cjv[8] = {cjA.x, cjA.y, cjA.z, cjA.w, cjB.x, cjB.y, cjB.z, cjB.w};

    if (diag && tx == ty) {
#pragma unroll
        for (int r = 0; r < 8; r++) m[r][r] = 0.f;
    }

#pragma unroll
    for (int r = 0; r < 8; r++) {
        float ai = aiv[r];
        *(float4*)&P2b[(size_t)(ib + r) * NP + jb] =
            make_float4(ai * m[r][0] * cjv[0], ai * m[r][1] * cjv[1],
                        ai * m[r][2] * cjv[2], ai * m[r][3] * cjv[3]);
        *(float4*)&P2b[(size_t)(ib + r) * NP + jb + 4] =
            make_float4(ai * m[r][4] * cjv[4], ai * m[r][5] * cjv[5],
                        ai * m[r][6] * cjv[6], ai * m[r][7] * cjv[7]);
    }

    if (!diag) {
        float4 ciA = *(const float4*)&g_c[soff + ib];
        float4 ciB = *(const float4*)&g_c[soff + ib + 4];
        float4 ajA = *(const float4*)&g_a[soff + jb];
        float4 ajB = *(const float4*)&g_a[soff + jb + 4];
        float civ[8] = {ciA.x, ciA.y, ciA.z, ciA.w, ciB.x, ciB.y, ciB.z, ciB.w};
        float ajv[8] = {ajA.x, ajA.y, ajA.z, ajA.w, ajB.x, ajB.y, ajB.z, ajB.w};
#pragma unroll
        for (int q = 0; q < 8; q++) {
            float aj = ajv[q];
            *(float4*)&P2b[(size_t)(jb + q) * NP + ib] =
                make_float4(aj * m[0][q] * civ[0], aj * m[1][q] * civ[1],
                            aj * m[2][q] * civ[2], aj * m[3][q] * civ[3]);
            *(float4*)&P2b[(size_t)(jb + q) * NP + ib + 4] =
                make_float4(aj * m[4][q] * civ[4], aj * m[5][q] * civ[5],
                            aj * m[6][q] * civ[6], aj * m[7][q] * civ[7]);
        }
    }
}

// ---------- K5a: order-1 segments (0, 2), flat float4 ----------
__global__ void __launch_bounds__(256) k_out1(float* __restrict__ out)
{
    unsigned f = blockIdx.x * 256 + threadIdx.x;
    if (f >= OUTQ) return;
    unsigned e0 = f * 4;
    unsigned ng = e0 / 750u;
    unsigned pos = e0 - ng * 750u;
    unsigned sl = ng / 250u;
    unsigned nn = ng - sl * 250u;

    float v1[4];
    unsigned pe = pos;
#pragma unroll
    for (int e = 0; e < 4; e++) {
        if (pe >= 750u) { pe -= 750u; nn += 1; if (nn == 250u) { nn = 0; sl += 1; } }
        unsigned m = pe;
        if (m >= 500u) m -= 500u; else if (m >= 250u) m -= 250u;
        float s = g_S[((size_t)sl * SROW + nn) * NP + m];
        float a = g_a[sl * NP + nn];
        float c = g_c[sl * NP + m];
        v1[e] = (m == nn) ? 0.f : a * s * c;
        pe += 1;
    }
    float4 V1 = make_float4(v1[0], v1[1], v1[2], v1[3]);
    *(float4*)&out[e0]           = V1;
    *(float4*)&out[2 * SEG + e0] = V1;
}

// ---------- K5b: order-2 segments (1, 3), flat float4 ----------
__global__ void __launch_bounds__(256) k_out2(float* __restrict__ out)
{
    unsigned f = blockIdx.x * 256 + threadIdx.x;
    if (f >= OUTQ) return;
    unsigned e0 = f * 4;
    unsigned ng = e0 / 750u;
    unsigned pos = e0 - ng * 750u;
    unsigned sl = ng / 250u;
    unsigned nn = ng - sl * 250u;

    float v2[4];
    unsigned pe = pos;
#pragma unroll
    for (int e = 0; e < 4; e++) {
        if (pe >= 750u) { pe -= 750u; nn += 1; if (nn == 250u) { nn = 0; sl += 1; } }
        unsigned m = pe;
        if (m >= 500u) m -= 500u; else if (m >= 250u) m -= 250u;
        v2[e] = g_P2[((size_t)sl * SROW + nn) * NP + m];
        pe += 1;
    }
    float4 V2 = make_float4(v2[0], v2[1], v2[2], v2[3]);
    *(float4*)&out[SEG + e0]     = V2;
    *(float4*)&out[3 * SEG + e0] = V2;
}

extern "C" void kernel_launch(void* const* d_in, const int* in_sizes, int n_in,
                              void* d_out, int out_size)
{
    const float* hist  = (const float*)d_in[0];
    const float* prior = (const float*)d_in[1];
    const float* obs   = (const float*)d_in[2];
    const float* W     = (const float*)d_in[3];
    const float* bias  = (const float*)d_in[4];
    float* out = (float*)d_out;

    // one-time resource init (handles only; identical launched work every call)
    static cudaStream_t s2 = nullptr;
    static cudaEvent_t evFork = nullptr, evJoin = nullptr;
    if (s2 == nullptr) {
        cudaStreamCreateWithFlags(&s2, cudaStreamNonBlocking);
        cudaEventCreateWithFlags(&evFork, cudaEventDisableTiming);
        cudaEventCreateWithFlags(&evJoin, cudaEventDisableTiming);
    }

    k_embed   <<<1500, 256>>>(hist, prior, obs, W, bias);
    k_sim     <<<dim3(3, SLICES), 256>>>();
    k_scal_t  <<<dim3(4, SLICES), 256>>>();
    k_scal_fin<<<SLICES, 256>>>();

    // fork: out1 (order-1 segments) runs concurrently with gemm2
    cudaEventRecord(evFork, 0);
    cudaStreamWaitEvent(s2, evFork, 0);

    k_gemm2<<<dim3(3, SLICES), 256>>>();
    k_out1 <<<(OUTQ + 255) / 256, 256, 0, s2>>>(out);

    cudaEventRecord(evJoin, s2);
    cudaStreamWaitEvent(0, evJoin, 0);

    k_out2 <<<(OUTQ + 255) / 256, 256>>>(out);
}